// round 16
// baseline (speedup 1.0000x reference)
#include <cuda_runtime.h>
#include <math.h>
#include <stdint.h>

// Problem constants
#define NN_   16384      // total nodes (B*N)
#define E_    262144     // edges (no self loops)
#define B_    64         // graphs
#define FIN_  256
#define OUTC_ 256
#define DEP_  64
#define HID_  256
#define G3_   768        // 3*HID

// ---------------- device scratch (no cudaMalloc allowed) ----------------
__device__ __align__(16) float g_Ax  [NN_*OUTC_];
__device__ float g_deg [NN_];
__device__ float g_dinv[NN_];
__device__ __align__(16) float g_agg [NN_*OUTC_];
__device__ __align__(16) float g_seqA[NN_*OUTC_];
__device__ __align__(16) float g_seqB[NN_*OUTC_];
__device__ __align__(16) float g_xp  [NN_*G3_];
__device__ float g_Bself[OUTC_];
__device__ float g_pool[B_*1280];

#define BUF_AX   1
#define BUF_SEQA 2
#define BUF_SEQB 3
#define BUF_XP   4
__device__ __forceinline__ float* pick_buf(int sel) {
    switch (sel) {
        case BUF_AX:   return g_Ax;
        case BUF_SEQA: return g_seqA;
        case BUF_SEQB: return g_seqB;
        default:       return g_xp;
    }
}

// ---------------- packed f32x2 + cluster + atomic helpers ----------------
__device__ __forceinline__ void ffma2(unsigned long long &d,
                                      unsigned long long a,
                                      unsigned long long b) {
    asm("fma.rn.f32x2 %0, %1, %2, %0;" : "+l"(d) : "l"(a), "l"(b));
}
__device__ __forceinline__ float hadd2(unsigned long long v) {
    float lo, hi;
    asm("mov.b64 {%0, %1}, %2;" : "=f"(lo), "=f"(hi) : "l"(v));
    return lo + hi;
}
__device__ __forceinline__ uint32_t smem_u32(const void* p) {
    uint32_t a;
    asm("{ .reg .u64 t; cvta.to.shared.u64 t, %1; cvt.u32.u64 %0, t; }"
        : "=r"(a) : "l"(p));
    return a;
}
__device__ __forceinline__ uint32_t ctarank() {
    uint32_t r; asm("mov.u32 %0, %%cluster_ctarank;" : "=r"(r)); return r;
}
__device__ __forceinline__ void st_cluster_f32(uint32_t laddr, uint32_t rank, float v) {
    uint32_t raddr;
    asm volatile("mapa.shared::cluster.u32 %0, %1, %2;" : "=r"(raddr) : "r"(laddr), "r"(rank));
    asm volatile("st.shared::cluster.f32 [%0], %1;" :: "r"(raddr), "f"(v) : "memory");
}
__device__ __forceinline__ void red_add_v4(float* addr, float a, float b, float c, float d) {
    asm volatile("red.global.add.v4.f32 [%0], {%1, %2, %3, %4};"
                 :: "l"(addr), "f"(a), "f"(b), "f"(c), "f"(d) : "memory");
}
#define CLUSTER_SYNC() do { \
    asm volatile("barrier.cluster.arrive.aligned;" ::: "memory"); \
    asm volatile("barrier.cluster.wait.aligned;" ::: "memory"); } while (0)

// ---------------- math helpers ----------------
__device__ __forceinline__ float fast_tanh(float x) {
    x = fminf(fmaxf(x, -15.f), 15.f);
    float e = __expf(2.f * x);
    return __fdividef(e - 1.f, e + 1.f);
}
__device__ __forceinline__ float fast_sig(float x) {
    x = fminf(fmaxf(x, -30.f), 30.f);
    return __fdividef(1.f, 1.f + __expf(-x));
}

// ---------------- sgemm3: FFMA2, conflict-free, C[M,N]=A[M,K]@W[N,K]^T ----
// BM=256, BN=64, BK=16; 256 threads; per-thread 16 rows x 4 strided cols.
// Smem [k2][row] float2: a-reads broadcast (2 addrs/warp), b-reads lane-
// consecutive float2 -> conflict-free. Accumulators k-pair packed.
#define BM3 256
#define BN3 64
#define BK3 16
__global__ void __launch_bounds__(256, 1)
sgemm3(const float* __restrict__ Aext, int aSel, const float* __restrict__ W,
       const float* __restrict__ bias, int cSel, int N, int K)
{
    const float* A = (aSel == 0) ? Aext : pick_buf(aSel);
    float* C = pick_buf(cSel);

    __shared__ __align__(16) float2 As2[BK3/2][BM3];   // [k2][m]
    __shared__ __align__(16) float2 Bs2[BK3/2][BN3];   // [k2][n]
    int tid = threadIdx.x;
    int mBase = blockIdx.y * BM3;
    int nBase = blockIdx.x * BN3;
    int ty = tid >> 4;   // 0..15 -> rows ty*16 .. ty*16+15
    int tx = tid & 15;   // cols tx + 16*j

    unsigned long long acc[16][4];
#pragma unroll
    for (int i = 0; i < 16; i++)
#pragma unroll
        for (int j = 0; j < 4; j++) acc[i][j] = 0ull;

    for (int kt = 0; kt < K; kt += BK3) {
        // A tile: 256 rows x 16 k = 1024 float4 -> 4 per thread
#pragma unroll
        for (int u = 0; u < 4; u++) {
            int v = tid + u * 256;
            int row = v >> 2;
            int kk = (v & 3) * 4;
            float4 a = *reinterpret_cast<const float4*>(&A[(size_t)(mBase + row) * K + kt + kk]);
            As2[kk / 2][row]     = make_float2(a.x, a.y);
            As2[kk / 2 + 1][row] = make_float2(a.z, a.w);
        }
        // B tile: 64 rows x 16 k = 256 float4 -> 1 per thread
        {
            int n = tid >> 2;
            int kk = (tid & 3) * 4;
            float4 b = *reinterpret_cast<const float4*>(&W[(size_t)(nBase + n) * K + kt + kk]);
            Bs2[kk / 2][n]     = make_float2(b.x, b.y);
            Bs2[kk / 2 + 1][n] = make_float2(b.z, b.w);
        }
        __syncthreads();
#pragma unroll
        for (int k2 = 0; k2 < BK3 / 2; k2++) {
            ulonglong2 a2[8];
            unsigned long long b2[4];
#pragma unroll
            for (int i = 0; i < 8; i++)   // 2 rows per 16B load, broadcast
                a2[i] = *reinterpret_cast<const ulonglong2*>(&As2[k2][ty * 16 + 2 * i]);
#pragma unroll
            for (int j = 0; j < 4; j++)   // lane-consecutive float2
                b2[j] = *reinterpret_cast<const unsigned long long*>(&Bs2[k2][tx + 16 * j]);
#pragma unroll
            for (int i = 0; i < 8; i++) {
#pragma unroll
                for (int j = 0; j < 4; j++) {
                    ffma2(acc[2 * i][j],     a2[i].x, b2[j]);
                    ffma2(acc[2 * i + 1][j], a2[i].y, b2[j]);
                }
            }
        }
        __syncthreads();
    }
#pragma unroll
    for (int i = 0; i < 16; i++) {
        int row = mBase + ty * 16 + i;
#pragma unroll
        for (int j = 0; j < 4; j++) {
            int col = nBase + tx + 16 * j;
            float r = hadd2(acc[i][j]);
            if (bias) r += bias[col];
            C[(size_t)row * N + col] = r;
        }
    }
}

// ---------------- GCN helper kernels ----------------
__global__ void k_count(const int* __restrict__ ei) {
    int e = blockIdx.x * blockDim.x + threadIdx.x;
    if (e < E_) atomicAdd(&g_deg[ei[E_ + e]], 1.f);
}
__global__ void k_dinv2(const float* __restrict__ WB) {
    if (blockIdx.x < 64) {
        int i = blockIdx.x * 256 + threadIdx.x;
        float d = g_deg[i] + 1.f;       // + self loop
        g_deg[i] = d;
        g_dinv[i] = rsqrtf(d);
    } else {
        int j = threadIdx.x;
        float s = 0.f;
#pragma unroll
        for (int d = 0; d < DEP_; d++) s += WB[j * DEP_ + d];
        g_Bself[j] = s;
    }
}

// ---------------- fused edge kernel (measured near its floor; unchanged) --
__global__ void __launch_bounds__(256)
k_edge_fused(const float* __restrict__ ea, const float* __restrict__ WB,
             const int* __restrict__ ei)
{
    __shared__ float As[64][DEP_ + 1];
    __shared__ float Bs[64][DEP_ + 1];
    int tid = threadIdx.x;
    int mBase = blockIdx.y * 64;
    int nBase = blockIdx.x * 64;

#pragma unroll
    for (int u = 0; u < 4; u++) {
        int v = tid + u * 256;
        int row = v >> 4;
        int kk = (v & 15) * 4;
        float4 a = *reinterpret_cast<const float4*>(&ea[(size_t)(mBase + row) * DEP_ + kk]);
        As[row][kk + 0] = a.x; As[row][kk + 1] = a.y;
        As[row][kk + 2] = a.z; As[row][kk + 3] = a.w;
    }
#pragma unroll
    for (int u = 0; u < 4; u++) {
        int v = tid + u * 256;
        int n = v >> 4;
        int kk = (v & 15) * 4;
        float4 b = *reinterpret_cast<const float4*>(&WB[(size_t)(nBase + n) * DEP_ + kk]);
        Bs[n][kk + 0] = b.x; Bs[n][kk + 1] = b.y;
        Bs[n][kk + 2] = b.z; Bs[n][kk + 3] = b.w;
    }
    __syncthreads();

    int ty = tid >> 4;
    int tx = tid & 15;
    float acc[4][4];
#pragma unroll
    for (int i = 0; i < 4; i++)
#pragma unroll
        for (int j = 0; j < 4; j++) acc[i][j] = 0.f;

#pragma unroll 8
    for (int k = 0; k < DEP_; k++) {
        float a[4], b[4];
#pragma unroll
        for (int i = 0; i < 4; i++) a[i] = As[ty * 4 + i][k];
#pragma unroll
        for (int j = 0; j < 4; j++) b[j] = Bs[tx * 4 + j][k];
#pragma unroll
        for (int i = 0; i < 4; i++)
#pragma unroll
            for (int j = 0; j < 4; j++) acc[i][j] = fmaf(a[i], b[j], acc[i][j]);
    }

#pragma unroll
    for (int i = 0; i < 4; i++) {
        int e = mBase + ty * 4 + i;
        int row = ei[e];
        int col = ei[E_ + e];
        float norm = g_dinv[row] * g_dinv[col];
        const float* axp = &g_Ax[(size_t)row * 256 + nBase + tx * 4];
        float* aggp = &g_agg[(size_t)col * 256 + nBase + tx * 4];
        red_add_v4(aggp,
                   norm * fast_tanh(axp[0] * acc[i][0]),
                   norm * fast_tanh(axp[1] * acc[i][1]),
                   norm * fast_tanh(axp[2] * acc[i][2]),
                   norm * fast_tanh(axp[3] * acc[i][3]));
    }
}

__global__ void k_final_node(const float* __restrict__ bias) {
    int i = blockIdx.x;
    int j = threadIdx.x;
    float dv = g_dinv[i];
    size_t idx = (size_t)i * 256 + j;
    float self = dv * dv * fast_tanh(g_Ax[idx] * g_Bself[j]);
    float v = (g_agg[idx] + self) * __fdividef(1.f, g_deg[i]);
    g_seqA[idx] = fast_tanh(v + bias[j]);
}

// tail: restore g_agg/g_deg to zero for the next replay
__global__ void k_tail() {
    int b = blockIdx.x, j = threadIdx.x;
    g_agg[(size_t)b * 256 + j] = 0.f;
    if (j == 0) g_deg[b] = 0.f;
}

// ---------------- clustered GRU (unchanged) ----------------
#define GRU_SMEM_FLOATS (192*256 + 2*2*256 + 2*192)
#define GRU_SMEM_BYTES  (GRU_SMEM_FLOATS * 4)

__global__ void __launch_bounds__(256, 1) __cluster_dims__(4, 1, 1)
k_gru(const float* __restrict__ whh, const float* __restrict__ b_hh,
      int outSel, int layer)
{
    extern __shared__ __align__(16) float smem[];
    float* w_s  = smem;                       // [64][192] float4 = [k4][local row]
    float* h_s  = smem + 192 * 256;           // [2][2][256] phase/graph/unit
    float* gh_s = h_s + 2 * 2 * 256;          // [2][192]

    float* seq_out = pick_buf(outSel);
    int tid = threadIdx.x;
    uint32_t rank = ctarank();
    int b0 = (blockIdx.x >> 2) * 2;

    const float4* w4 = reinterpret_cast<const float4*>(whh);
    float4* ws4 = reinterpret_cast<float4*>(w_s);
    for (int v = tid; v < 192 * 64; v += 256) {
        int lr = v % 192, k4 = v / 192;
        int grow = (lr >> 6) * 256 + (int)rank * 64 + (lr & 63);
        ws4[k4 * 192 + lr] = w4[grow * 64 + k4];
    }
    if (tid < 256) { h_s[tid] = 0.f; h_s[256 + tid] = 0.f; }
    __syncthreads();
    CLUSTER_SYNC();

    float my_bias = 0.f;
    if (tid < 192)
        my_bias = b_hh[(tid >> 6) * 256 + (int)rank * 64 + (tid & 63)];
    int gsel = (tid >> 6) & 1;
    int j_loc = tid & 63;
    int jg = (int)rank * 64 + j_loc;
    const float* xbase = g_xp + (size_t)(b0 + gsel) * 256 * 768;
    uint32_t h_s_base = smem_u32(h_s);
    const ulonglong2* wsv = reinterpret_cast<const ulonglong2*>(w_s);

    float hn = 0.f;
    for (int t = 0; t < 256; t++) {
        int ph = t & 1;
        float xr = 0.f, xz = 0.f, xn = 0.f;
        if (tid < 128) {
            const float* xv = xbase + (size_t)t * 768;
            xr = xv[jg]; xz = xv[256 + jg]; xn = xv[512 + jg];
        }
        if (tid < 192) {
            const ulonglong2* hva = reinterpret_cast<const ulonglong2*>(&h_s[ph * 512]);
            const ulonglong2* hvb = reinterpret_cast<const ulonglong2*>(&h_s[ph * 512 + 256]);
            unsigned long long a0 = 0ull, a1 = 0ull;
#pragma unroll 8
            for (int k4 = 0; k4 < 64; k4++) {
                ulonglong2 w = wsv[k4 * 192 + tid];
                ulonglong2 ha = hva[k4];
                ulonglong2 hb = hvb[k4];
                ffma2(a0, w.x, ha.x); ffma2(a0, w.y, ha.y);
                ffma2(a1, w.x, hb.x); ffma2(a1, w.y, hb.y);
            }
            gh_s[tid]       = hadd2(a0) + my_bias;
            gh_s[192 + tid] = hadd2(a1) + my_bias;
        }
        __syncthreads();
        if (tid < 128) {
            const float* gh = &gh_s[gsel * 192];
            float r = fast_sig(xr + gh[j_loc]);
            float z = fast_sig(xz + gh[64 + j_loc]);
            float n = fast_tanh(xn + r * gh[128 + j_loc]);
            float hp = h_s[ph * 512 + gsel * 256 + jg];
            hn = (1.f - z) * n + z * hp;
            uint32_t laddr = h_s_base + (uint32_t)(((ph ^ 1) * 512 + gsel * 256 + jg) * 4);
#pragma unroll
            for (uint32_t r4 = 0; r4 < 4; r4++) st_cluster_f32(laddr, r4, hn);
            seq_out[((size_t)(b0 + gsel) * 256 + t) * 256 + jg] = hn;
        }
        CLUSTER_SYNC();
    }

    if (tid < 128)
        g_pool[(b0 + gsel) * 1280 + layer * 256 + jg] = hn;
}

// ---------------- pooling + head ----------------
__global__ void k_pool(int seqSel) {
    const float* seq = pick_buf(seqSel);
    int b = blockIdx.x, j = threadIdx.x;
    float m = -1e30f, s = 0.f;
#pragma unroll 4
    for (int t = 0; t < 256; t++) {
        float v = seq[((size_t)b * 256 + t) * 256 + j];
        m = fmaxf(m, v);
        s += v;
    }
    g_pool[b * 1280 + 768 + j] = m;
    g_pool[b * 1280 + 1024 + j] = s * (1.f / 256.f);
}

__global__ void k_head(const float* __restrict__ linW, const float* __restrict__ linb,
                       float* __restrict__ out)
{
    __shared__ float red0[128], red1[128];
    int b = blockIdx.x, tid = threadIdx.x;
    float p0 = 0.f, p1 = 0.f;
    for (int i = tid; i < 1280; i += 128) {
        float pv = g_pool[b * 1280 + i];
        p0 = fmaf(pv, linW[i], p0);
        p1 = fmaf(pv, linW[1280 + i], p1);
    }
    red0[tid] = p0; red1[tid] = p1;
    __syncthreads();
    for (int s = 64; s > 0; s >>= 1) {
        if (tid < s) { red0[tid] += red0[tid + s]; red1[tid] += red1[tid + s]; }
        __syncthreads();
    }
    if (tid == 0) {
        float l0 = red0[0] + linb[0];
        float l1 = red1[0] + linb[1];
        float mm = fmaxf(l0, l1);
        float e0 = __expf(l0 - mm), e1 = __expf(l1 - mm);
        float inv = __fdividef(1.f, e0 + e1);
        out[b * 2 + 0] = e0 * inv;
        out[b * 2 + 1] = e1 * inv;
    }
}

// ---------------- launch ----------------
extern "C" void kernel_launch(void* const* d_in, const int* in_sizes, int n_in,
                              void* d_out, int out_size)
{
    (void)in_sizes; (void)n_in; (void)out_size;
    const float* x    = (const float*)d_in[0];
    const float* ea   = (const float*)d_in[1];
    const int*   ei   = (const int*)  d_in[2];
    const float* WA   = (const float*)d_in[3];
    const float* WB   = (const float*)d_in[4];
    const float* gb   = (const float*)d_in[5];
    const float* wih[3] = {(const float*)d_in[6],  (const float*)d_in[10], (const float*)d_in[14]};
    const float* whh[3] = {(const float*)d_in[7],  (const float*)d_in[11], (const float*)d_in[15]};
    const float* bih[3] = {(const float*)d_in[8],  (const float*)d_in[12], (const float*)d_in[16]};
    const float* bhh[3] = {(const float*)d_in[9],  (const float*)d_in[13], (const float*)d_in[17]};
    const float* linW = (const float*)d_in[18];
    const float* linb = (const float*)d_in[19];
    float* out = (float*)d_out;

    cudaFuncSetAttribute(k_gru, cudaFuncAttributeMaxDynamicSharedMemorySize,
                         GRU_SMEM_BYTES);

    // ---- GCN (k_edge_fused stays launch #4 -> ncu anchor) ----
    k_count<<<E_ / 256, 256>>>(ei);                                                // 1
    sgemm3 <<<dim3(OUTC_ / BN3, NN_ / BM3), 256>>>(x, 0, WA, nullptr, BUF_AX,
                                                   OUTC_, FIN_);                   // 2
    k_dinv2<<<65, 256>>>(WB);                                                      // 3
    k_edge_fused<<<dim3(OUTC_ / 64, E_ / 64), 256>>>(ea, WB, ei);                  // 4
    k_final_node<<<NN_, 256>>>(gb);                                                // 5
    k_tail<<<NN_, 256>>>();                                                        // 6

    // ---- GRU: 3 layers (ping-pong seqA <-> seqB) ----
    int sin = BUF_SEQA, sout = BUF_SEQB;
    for (int l = 0; l < 3; l++) {
        sgemm3<<<dim3(G3_ / BN3, NN_ / BM3), 256>>>(nullptr, sin, wih[l], bih[l],
                                                    BUF_XP, G3_, 256);
        k_gru<<<(B_ / 2) * 4, 256, GRU_SMEM_BYTES>>>(whh[l], bhh[l], sout, l);
        int tmp = sin; sin = sout; sout = tmp;
    }
    // final layer output in `sin`

    // ---- pool + head ----
    k_pool<<<B_, 256>>>(sin);
    k_head<<<B_, 128>>>(linW, linb, out);
}

// round 17
// speedup vs baseline: 1.1375x; 1.1375x over previous
#include <cuda_runtime.h>
#include <math.h>
#include <stdint.h>

// Problem constants
#define NN_   16384      // total nodes (B*N)
#define E_    262144     // edges (no self loops)
#define B_    64         // graphs
#define FIN_  256
#define OUTC_ 256
#define DEP_  64
#define HID_  256
#define G3_   768        // 3*HID

// ---------------- device scratch (no cudaMalloc allowed) ----------------
// __device__ globals are zero-initialized at load; k_final_node re-zeroes
// g_agg/g_deg after consuming them so every graph replay starts clean.
__device__ __align__(16) float g_Ax  [NN_*OUTC_];
__device__ float g_deg [NN_];
__device__ float g_dinv[NN_];
__device__ __align__(16) float g_agg [NN_*OUTC_];
__device__ __align__(16) float g_seqA[NN_*OUTC_];
__device__ __align__(16) float g_seqB[NN_*OUTC_];
__device__ __align__(16) float g_xp  [NN_*G3_];
__device__ float g_Bself[OUTC_];
__device__ float g_pool[B_*1280];

#define BUF_AX   1
#define BUF_SEQA 2
#define BUF_SEQB 3
#define BUF_XP   4
__device__ __forceinline__ float* pick_buf(int sel) {
    switch (sel) {
        case BUF_AX:   return g_Ax;
        case BUF_SEQA: return g_seqA;
        case BUF_SEQB: return g_seqB;
        default:       return g_xp;
    }
}

// ---------------- packed f32x2 + cluster + atomic helpers ----------------
__device__ __forceinline__ void ffma2(unsigned long long &d,
                                      unsigned long long a,
                                      unsigned long long b) {
    asm("fma.rn.f32x2 %0, %1, %2, %0;" : "+l"(d) : "l"(a), "l"(b));
}
__device__ __forceinline__ float hadd2(unsigned long long v) {
    float lo, hi;
    asm("mov.b64 {%0, %1}, %2;" : "=f"(lo), "=f"(hi) : "l"(v));
    return lo + hi;
}
__device__ __forceinline__ uint32_t smem_u32(const void* p) {
    uint32_t a;
    asm("{ .reg .u64 t; cvta.to.shared.u64 t, %1; cvt.u32.u64 %0, t; }"
        : "=r"(a) : "l"(p));
    return a;
}
__device__ __forceinline__ uint32_t ctarank() {
    uint32_t r; asm("mov.u32 %0, %%cluster_ctarank;" : "=r"(r)); return r;
}
__device__ __forceinline__ void st_cluster_f32(uint32_t laddr, uint32_t rank, float v) {
    uint32_t raddr;
    asm volatile("mapa.shared::cluster.u32 %0, %1, %2;" : "=r"(raddr) : "r"(laddr), "r"(rank));
    asm volatile("st.shared::cluster.f32 [%0], %1;" :: "r"(raddr), "f"(v) : "memory");
}
__device__ __forceinline__ void red_add_v4(float* addr, float a, float b, float c, float d) {
    asm volatile("red.global.add.v4.f32 [%0], {%1, %2, %3, %4};"
                 :: "l"(addr), "f"(a), "f"(b), "f"(c), "f"(d) : "memory");
}
#define CLUSTER_SYNC() do { \
    asm volatile("barrier.cluster.arrive.aligned;" ::: "memory"); \
    asm volatile("barrier.cluster.wait.aligned;" ::: "memory"); } while (0)
#define CLUSTER_ARRIVE() asm volatile("barrier.cluster.arrive.aligned;" ::: "memory")
#define CLUSTER_WAIT()   asm volatile("barrier.cluster.wait.aligned;" ::: "memory")

// ---------------- math helpers ----------------
__device__ __forceinline__ float fast_tanh(float x) {
    x = fminf(fmaxf(x, -15.f), 15.f);
    float e = __expf(2.f * x);
    return __fdividef(e - 1.f, e + 1.f);
}
__device__ __forceinline__ float fast_sig(float x) {
    x = fminf(fmaxf(x, -30.f), 30.f);
    return __fdividef(1.f, 1.f + __expf(-x));
}

// ---------------- SGEMM 128x128 scalar (measured-best) ---------------
#define BM2 128
#define BN2 128
#define BK2 16
__global__ void __launch_bounds__(256)
sgemm2(const float* __restrict__ Aext, int aSel, const float* __restrict__ W,
       const float* __restrict__ bias, int cSel, int N, int K)
{
    const float* A = (aSel == 0) ? Aext : pick_buf(aSel);
    float* C = pick_buf(cSel);

    __shared__ float As[BK2][BM2 + 4];
    __shared__ float Bs[BK2][BN2 + 4];
    int tid = threadIdx.x;
    int mBase = blockIdx.y * BM2;
    int nBase = blockIdx.x * BN2;
    int ty = tid >> 4;
    int tx = tid & 15;

    float acc[8][8];
#pragma unroll
    for (int i = 0; i < 8; i++)
#pragma unroll
        for (int j = 0; j < 8; j++) acc[i][j] = 0.f;

    for (int kt = 0; kt < K; kt += BK2) {
#pragma unroll
        for (int u = 0; u < 2; u++) {
            int v = tid + u * 256;
            int row = v >> 2;
            int kk = (v & 3) * 4;
            float4 a = *reinterpret_cast<const float4*>(&A[(size_t)(mBase + row) * K + kt + kk]);
            As[kk + 0][row] = a.x; As[kk + 1][row] = a.y;
            As[kk + 2][row] = a.z; As[kk + 3][row] = a.w;
        }
#pragma unroll
        for (int u = 0; u < 2; u++) {
            int v = tid + u * 256;
            int n = v >> 2;
            int kk = (v & 3) * 4;
            float4 b = *reinterpret_cast<const float4*>(&W[(size_t)(nBase + n) * K + kt + kk]);
            Bs[kk + 0][n] = b.x; Bs[kk + 1][n] = b.y;
            Bs[kk + 2][n] = b.z; Bs[kk + 3][n] = b.w;
        }
        __syncthreads();
#pragma unroll
        for (int k = 0; k < BK2; k++) {
            float a[8], b[8];
            float4 a0 = *reinterpret_cast<const float4*>(&As[k][ty * 8]);
            float4 a1 = *reinterpret_cast<const float4*>(&As[k][ty * 8 + 4]);
            float4 b0 = *reinterpret_cast<const float4*>(&Bs[k][tx * 8]);
            float4 b1 = *reinterpret_cast<const float4*>(&Bs[k][tx * 8 + 4]);
            a[0]=a0.x; a[1]=a0.y; a[2]=a0.z; a[3]=a0.w;
            a[4]=a1.x; a[5]=a1.y; a[6]=a1.z; a[7]=a1.w;
            b[0]=b0.x; b[1]=b0.y; b[2]=b0.z; b[3]=b0.w;
            b[4]=b1.x; b[5]=b1.y; b[6]=b1.z; b[7]=b1.w;
#pragma unroll
            for (int i = 0; i < 8; i++)
#pragma unroll
                for (int j = 0; j < 8; j++) acc[i][j] = fmaf(a[i], b[j], acc[i][j]);
        }
        __syncthreads();
    }
#pragma unroll
    for (int i = 0; i < 8; i++) {
        int row = mBase + ty * 8 + i;
        int col = nBase + tx * 8;
#pragma unroll
        for (int h = 0; h < 2; h++) {
            float4 r = make_float4(acc[i][h*4+0], acc[i][h*4+1], acc[i][h*4+2], acc[i][h*4+3]);
            if (bias) {
                r.x += bias[col + h*4 + 0]; r.y += bias[col + h*4 + 1];
                r.z += bias[col + h*4 + 2]; r.w += bias[col + h*4 + 3];
            }
            *reinterpret_cast<float4*>(&C[(size_t)row * N + col + h*4]) = r;
        }
    }
}

// ---------------- GCN helper kernels ----------------
__global__ void k_count(const int* __restrict__ ei) {
    int e = blockIdx.x * blockDim.x + threadIdx.x;
    if (e < E_) atomicAdd(&g_deg[ei[E_ + e]], 1.f);
}
__global__ void k_dinv2(const float* __restrict__ WB) {
    if (blockIdx.x < 64) {
        int i = blockIdx.x * 256 + threadIdx.x;
        float d = g_deg[i] + 1.f;       // + self loop
        g_deg[i] = d;
        g_dinv[i] = rsqrtf(d);
    } else {
        int j = threadIdx.x;
        float s = 0.f;
#pragma unroll
        for (int d = 0; d < DEP_; d++) s += WB[j * DEP_ + d];
        g_Bself[j] = s;
    }
}

// ---------------- fused edge kernel (measured near floor; unchanged) -----
__global__ void __launch_bounds__(256)
k_edge_fused(const float* __restrict__ ea, const float* __restrict__ WB,
             const int* __restrict__ ei)
{
    __shared__ float As[64][DEP_ + 1];
    __shared__ float Bs[64][DEP_ + 1];
    int tid = threadIdx.x;
    int mBase = blockIdx.y * 64;
    int nBase = blockIdx.x * 64;

#pragma unroll
    for (int u = 0; u < 4; u++) {
        int v = tid + u * 256;
        int row = v >> 4;
        int kk = (v & 15) * 4;
        float4 a = *reinterpret_cast<const float4*>(&ea[(size_t)(mBase + row) * DEP_ + kk]);
        As[row][kk + 0] = a.x; As[row][kk + 1] = a.y;
        As[row][kk + 2] = a.z; As[row][kk + 3] = a.w;
    }
#pragma unroll
    for (int u = 0; u < 4; u++) {
        int v = tid + u * 256;
        int n = v >> 4;
        int kk = (v & 15) * 4;
        float4 b = *reinterpret_cast<const float4*>(&WB[(size_t)(nBase + n) * DEP_ + kk]);
        Bs[n][kk + 0] = b.x; Bs[n][kk + 1] = b.y;
        Bs[n][kk + 2] = b.z; Bs[n][kk + 3] = b.w;
    }
    __syncthreads();

    int ty = tid >> 4;
    int tx = tid & 15;
    float acc[4][4];
#pragma unroll
    for (int i = 0; i < 4; i++)
#pragma unroll
        for (int j = 0; j < 4; j++) acc[i][j] = 0.f;

#pragma unroll 8
    for (int k = 0; k < DEP_; k++) {
        float a[4], b[4];
#pragma unroll
        for (int i = 0; i < 4; i++) a[i] = As[ty * 4 + i][k];
#pragma unroll
        for (int j = 0; j < 4; j++) b[j] = Bs[tx * 4 + j][k];
#pragma unroll
        for (int i = 0; i < 4; i++)
#pragma unroll
            for (int j = 0; j < 4; j++) acc[i][j] = fmaf(a[i], b[j], acc[i][j]);
    }

#pragma unroll
    for (int i = 0; i < 4; i++) {
        int e = mBase + ty * 4 + i;
        int row = ei[e];
        int col = ei[E_ + e];
        float norm = g_dinv[row] * g_dinv[col];
        const float* axp = &g_Ax[(size_t)row * 256 + nBase + tx * 4];
        float* aggp = &g_agg[(size_t)col * 256 + nBase + tx * 4];
        red_add_v4(aggp,
                   norm * fast_tanh(axp[0] * acc[i][0]),
                   norm * fast_tanh(axp[1] * acc[i][1]),
                   norm * fast_tanh(axp[2] * acc[i][2]),
                   norm * fast_tanh(axp[3] * acc[i][3]));
    }
}

// final node + integrated tail (re-zero agg/deg for next replay)
__global__ void k_final_node(const float* __restrict__ bias) {
    int i = blockIdx.x;
    int j = threadIdx.x;
    float d = g_deg[i];
    float dv = g_dinv[i];
    size_t idx = (size_t)i * 256 + j;
    float self = dv * dv * fast_tanh(g_Ax[idx] * g_Bself[j]);
    float v = (g_agg[idx] + self) * __fdividef(1.f, d);
    g_seqA[idx] = fast_tanh(v + bias[j]);
    g_agg[idx] = 0.f;
    __syncthreads();                 // all reads of g_deg[i] complete
    if (j == 0) g_deg[i] = 0.f;
}

// ---------------- clustered GRU ----------------
// 4-CTA cluster per 2 graphs; rank owns units [rank*64, rank*64+64);
// weight slice smem-resident in conflict-free [k4][row] layout.
// Cluster barrier split arrive/wait: seq_out store + next-step x prefetch
// execute inside the barrier latency window.
#define GRU_SMEM_FLOATS (192*256 + 2*2*256 + 2*192)
#define GRU_SMEM_BYTES  (GRU_SMEM_FLOATS * 4)

__global__ void __launch_bounds__(256, 1) __cluster_dims__(4, 1, 1)
k_gru(const float* __restrict__ whh, const float* __restrict__ b_hh,
      int outSel, int layer)
{
    extern __shared__ __align__(16) float smem[];
    float* w_s  = smem;                       // [64][192] float4 = [k4][local row]
    float* h_s  = smem + 192 * 256;           // [2][2][256] phase/graph/unit
    float* gh_s = h_s + 2 * 2 * 256;          // [2][192]

    float* seq_out = pick_buf(outSel);
    int tid = threadIdx.x;
    uint32_t rank = ctarank();
    int b0 = (blockIdx.x >> 2) * 2;

    const float4* w4 = reinterpret_cast<const float4*>(whh);
    float4* ws4 = reinterpret_cast<float4*>(w_s);
    for (int v = tid; v < 192 * 64; v += 256) {
        int lr = v % 192, k4 = v / 192;
        int grow = (lr >> 6) * 256 + (int)rank * 64 + (lr & 63);
        ws4[k4 * 192 + lr] = w4[grow * 64 + k4];
    }
    if (tid < 256) { h_s[tid] = 0.f; h_s[256 + tid] = 0.f; }
    __syncthreads();
    CLUSTER_SYNC();

    float my_bias = 0.f;
    if (tid < 192)
        my_bias = b_hh[(tid >> 6) * 256 + (int)rank * 64 + (tid & 63)];
    int gsel = (tid >> 6) & 1;
    int j_loc = tid & 63;
    int jg = (int)rank * 64 + j_loc;
    const float* xbase = g_xp + (size_t)(b0 + gsel) * 256 * 768;
    uint32_t h_s_base = smem_u32(h_s);
    const ulonglong2* wsv = reinterpret_cast<const ulonglong2*>(w_s);

    // x-gate prefetch for t=0
    float xr = 0.f, xz = 0.f, xn = 0.f;
    if (tid < 128) { xr = xbase[jg]; xz = xbase[256 + jg]; xn = xbase[512 + jg]; }

    float hn = 0.f;
    for (int t = 0; t < 256; t++) {
        int ph = t & 1;
        if (tid < 192) {
            const ulonglong2* hva = reinterpret_cast<const ulonglong2*>(&h_s[ph * 512]);
            const ulonglong2* hvb = reinterpret_cast<const ulonglong2*>(&h_s[ph * 512 + 256]);
            unsigned long long a0 = 0ull, a1 = 0ull;
#pragma unroll 8
            for (int k4 = 0; k4 < 64; k4++) {
                ulonglong2 w = wsv[k4 * 192 + tid];
                ulonglong2 ha = hva[k4];
                ulonglong2 hb = hvb[k4];
                ffma2(a0, w.x, ha.x); ffma2(a0, w.y, ha.y);
                ffma2(a1, w.x, hb.x); ffma2(a1, w.y, hb.y);
            }
            gh_s[tid]       = hadd2(a0) + my_bias;
            gh_s[192 + tid] = hadd2(a1) + my_bias;
        }
        __syncthreads();
        if (tid < 128) {
            const float* gh = &gh_s[gsel * 192];
            float r = fast_sig(xr + gh[j_loc]);
            float z = fast_sig(xz + gh[64 + j_loc]);
            float n = fast_tanh(xn + r * gh[128 + j_loc]);
            float hp = h_s[ph * 512 + gsel * 256 + jg];
            hn = (1.f - z) * n + z * hp;
            uint32_t laddr = h_s_base + (uint32_t)(((ph ^ 1) * 512 + gsel * 256 + jg) * 4);
#pragma unroll
            for (uint32_t r4 = 0; r4 < 4; r4++) st_cluster_f32(laddr, r4, hn);
        }
        CLUSTER_ARRIVE();            // release: h stores visible after peers' wait
        // --- latency-hidden window: independent work ---
        if (tid < 128) {
            seq_out[((size_t)(b0 + gsel) * 256 + t) * 256 + jg] = hn;
            if (t < 255) {
                const float* xv = xbase + (size_t)(t + 1) * 768;
                xr = xv[jg]; xz = xv[256 + jg]; xn = xv[512 + jg];
            }
        }
        CLUSTER_WAIT();
    }

    if (tid < 128)
        g_pool[(b0 + gsel) * 1280 + layer * 256 + jg] = hn;
    CLUSTER_SYNC();                  // no CTA exits while peers may still write
}

// ---------------- pooling + head ----------------
__global__ void k_pool(int seqSel) {
    const float* seq = pick_buf(seqSel);
    int b = blockIdx.x, j = threadIdx.x;
    float m = -1e30f, s = 0.f;
#pragma unroll 4
    for (int t = 0; t < 256; t++) {
        float v = seq[((size_t)b * 256 + t) * 256 + j];
        m = fmaxf(m, v);
        s += v;
    }
    g_pool[b * 1280 + 768 + j] = m;
    g_pool[b * 1280 + 1024 + j] = s * (1.f / 256.f);
}

__global__ void k_head(const float* __restrict__ linW, const float* __restrict__ linb,
                       float* __restrict__ out)
{
    __shared__ float red0[128], red1[128];
    int b = blockIdx.x, tid = threadIdx.x;
    float p0 = 0.f, p1 = 0.f;
    for (int i = tid; i < 1280; i += 128) {
        float pv = g_pool[b * 1280 + i];
        p0 = fmaf(pv, linW[i], p0);
        p1 = fmaf(pv, linW[1280 + i], p1);
    }
    red0[tid] = p0; red1[tid] = p1;
    __syncthreads();
    for (int s = 64; s > 0; s >>= 1) {
        if (tid < s) { red0[tid] += red0[tid + s]; red1[tid] += red1[tid + s]; }
        __syncthreads();
    }
    if (tid == 0) {
        float l0 = red0[0] + linb[0];
        float l1 = red1[0] + linb[1];
        float mm = fmaxf(l0, l1);
        float e0 = __expf(l0 - mm), e1 = __expf(l1 - mm);
        float inv = __fdividef(1.f, e0 + e1);
        out[b * 2 + 0] = e0 * inv;
        out[b * 2 + 1] = e1 * inv;
    }
}

// ---------------- launch ----------------
extern "C" void kernel_launch(void* const* d_in, const int* in_sizes, int n_in,
                              void* d_out, int out_size)
{
    (void)in_sizes; (void)n_in; (void)out_size;
    const float* x    = (const float*)d_in[0];
    const float* ea   = (const float*)d_in[1];
    const int*   ei   = (const int*)  d_in[2];
    const float* WA   = (const float*)d_in[3];
    const float* WB   = (const float*)d_in[4];
    const float* gb   = (const float*)d_in[5];
    const float* wih[3] = {(const float*)d_in[6],  (const float*)d_in[10], (const float*)d_in[14]};
    const float* whh[3] = {(const float*)d_in[7],  (const float*)d_in[11], (const float*)d_in[15]};
    const float* bih[3] = {(const float*)d_in[8],  (const float*)d_in[12], (const float*)d_in[16]};
    const float* bhh[3] = {(const float*)d_in[9],  (const float*)d_in[13], (const float*)d_in[17]};
    const float* linW = (const float*)d_in[18];
    const float* linb = (const float*)d_in[19];
    float* out = (float*)d_out;

    cudaFuncSetAttribute(k_gru, cudaFuncAttributeMaxDynamicSharedMemorySize,
                         GRU_SMEM_BYTES);

    // ---- GCN (k_edge_fused stays launch #4 -> ncu anchor) ----
    k_count<<<E_ / 256, 256>>>(ei);                                                // 1
    sgemm2 <<<dim3(OUTC_ / BN2, NN_ / BM2), 256>>>(x, 0, WA, nullptr, BUF_AX,
                                                   OUTC_, FIN_);                   // 2
    k_dinv2<<<65, 256>>>(WB);                                                      // 3
    k_edge_fused<<<dim3(OUTC_ / 64, E_ / 64), 256>>>(ea, WB, ei);                  // 4
    k_final_node<<<NN_, 256>>>(gb);                                                // 5

    // ---- GRU: 3 layers (ping-pong seqA <-> seqB) ----
    int sin = BUF_SEQA, sout = BUF_SEQB;
    for (int l = 0; l < 3; l++) {
        sgemm2<<<dim3(G3_ / BN2, NN_ / BM2), 256>>>(nullptr, sin, wih[l], bih[l],
                                                    BUF_XP, G3_, 256);
        k_gru<<<(B_ / 2) * 4, 256, GRU_SMEM_BYTES>>>(whh[l], bhh[l], sout, l);
        int tmp = sin; sin = sout; sout = tmp;
    }
    // final layer output in `sin`

    // ---- pool + head ----
    k_pool<<<B_, 256>>>(sin);
    k_head<<<B_, 128>>>(linW, linb, out);
}